// round 1
// baseline (speedup 1.0000x reference)
#include <cuda_runtime.h>
#include <math.h>

#define S 1024
#define CS 768
#define CZ 128
#define DH 32
#define NH 24
#define NB 2
#define MROWS (NB*S)     // 2048
#define SSQ (S*S)        // 1048576
#define EPS 1e-5f
#define NEGINF (-1000000000.0f)

// ---------------- scratch (device globals; no allocation allowed) ----------------
__device__ float g_emb[NB*3*CS];            // shift|scale|gate per batch
__device__ float g_bsn[MROWS*CS];           // modulated LN(bs)
__device__ float g_qkvraw[3][MROWS*CS];     // raw q,k,v projections
__device__ float g_q[NB*NH*S*DH];
__device__ float g_k[NB*NH*S*DH];
__device__ float g_v[NB*NH*S*DH];
__device__ float g_A[CZ*NH];                // ln_z_w[c]*w_z[c,h]
__device__ float g_Bh[NH];                  // sum_c ln_z_b[c]*w_z[c,h]
__device__ float g_Ch[NH];                  // sum_c A[c,h]
__device__ float g_bias[NH*SSQ];            // per-head bias incl. mask  (100MB)
__device__ float g_oat[MROWS*CS];           // attention output [b,s,c]

// ---------------- kernel 1: tiny precompute for z-bias refactor ----------------
__global__ void prep_kernel(const float* __restrict__ ln_z_w,
                            const float* __restrict__ ln_z_b,
                            const float* __restrict__ w_z) {
    int h = threadIdx.x;
    if (h >= NH) return;
    float ch = 0.f, bh = 0.f;
    for (int c = 0; c < CZ; c++) {
        float wz = w_z[c*NH + h];
        float a = ln_z_w[c] * wz;
        g_A[c*NH + h] = a;
        ch += a;
        bh += ln_z_b[c] * wz;
    }
    g_Ch[h] = ch;
    g_Bh[h] = bh;
}

// ---------------- kernel 2: adaLN embedding: silu(t) @ w_adaln + b ----------------
__global__ __launch_bounds__(128) void adaln_kernel(const float* __restrict__ t,
                                                    const float* __restrict__ w_adaln,
                                                    const float* __restrict__ b_adaln) {
    __shared__ float st[CS];
    int b = blockIdx.y;
    int tid = threadIdx.x;
    for (int i = tid; i < CS; i += 128) {
        float v = t[b*CS + i];
        st[i] = v / (1.f + expf(-v));
    }
    __syncthreads();
    int j = blockIdx.x * 128 + tid;
    float acc = b_adaln[j];
    #pragma unroll 4
    for (int i = 0; i < CS; i++)
        acc += st[i] * w_adaln[i*(3*CS) + j];
    g_emb[b*(3*CS) + j] = acc;
}

// ---------------- kernel 3: LN(bs) * (1+scale) + shift ----------------
__global__ __launch_bounds__(256) void bsnorm_kernel(const float* __restrict__ bs) {
    __shared__ float red[16];
    int row = blockIdx.x;
    int b = row >> 10;
    int tid = threadIdx.x;
    float x[3];
    float s1 = 0.f, s2 = 0.f;
    #pragma unroll
    for (int j = 0; j < 3; j++) {
        int c = tid + j*256;
        float v = bs[(size_t)row*CS + c];
        x[j] = v;
        s1 += v;
        s2 += v*v;
    }
    #pragma unroll
    for (int off = 16; off >= 1; off >>= 1) {
        s1 += __shfl_xor_sync(0xffffffffu, s1, off);
        s2 += __shfl_xor_sync(0xffffffffu, s2, off);
    }
    int w = tid >> 5;
    if ((tid & 31) == 0) { red[w] = s1; red[8+w] = s2; }
    __syncthreads();
    float t1 = 0.f, t2 = 0.f;
    #pragma unroll
    for (int ww = 0; ww < 8; ww++) { t1 += red[ww]; t2 += red[8+ww]; }
    float mu = t1 * (1.f/CS);
    float var = t2 * (1.f/CS) - mu*mu;
    float rs = rsqrtf(var + EPS);
    #pragma unroll
    for (int j = 0; j < 3; j++) {
        int c = tid + j*256;
        float sc = g_emb[b*(3*CS) + CS + c];
        float sh = g_emb[b*(3*CS) + c];
        g_bsn[(size_t)row*CS + c] = (x[j]-mu)*rs*(1.f+sc) + sh;
    }
}

// ---------------- kernel 4: generic tiled fp32 GEMM (64x64x16, 4x4/thread) ----------------
// mode 0: C = A@B    mode 1: C = (A@B + bo) * gate   (gate from g_emb)
__global__ __launch_bounds__(256) void gemm_kernel(const float* __restrict__ A,
                                                   const float* __restrict__ Bw,
                                                   float* __restrict__ C,
                                                   int M, int N, int K,
                                                   int mode,
                                                   const float* __restrict__ bo) {
    __shared__ float As[16][68];
    __shared__ float Bs[16][68];
    int tid = threadIdx.x;
    int tx = tid & 15, ty = tid >> 4;
    int m0 = blockIdx.y * 64, n0 = blockIdx.x * 64;
    float acc[4][4] = {};
    int a_m = tid >> 2;
    int a_k = (tid & 3) * 4;
    int b_k = tid >> 4;
    int b_n = (tid & 15) * 4;
    for (int k0 = 0; k0 < K; k0 += 16) {
        float4 av = *(const float4*)&A[(size_t)(m0 + a_m)*K + k0 + a_k];
        float4 bv = *(const float4*)&Bw[(size_t)(k0 + b_k)*N + n0 + b_n];
        __syncthreads();
        As[a_k+0][a_m] = av.x; As[a_k+1][a_m] = av.y;
        As[a_k+2][a_m] = av.z; As[a_k+3][a_m] = av.w;
        *(float4*)&Bs[b_k][b_n] = bv;
        __syncthreads();
        #pragma unroll
        for (int kk = 0; kk < 16; kk++) {
            float4 a = *(float4*)&As[kk][4*ty];
            float4 b = *(float4*)&Bs[kk][4*tx];
            acc[0][0] += a.x*b.x; acc[0][1] += a.x*b.y; acc[0][2] += a.x*b.z; acc[0][3] += a.x*b.w;
            acc[1][0] += a.y*b.x; acc[1][1] += a.y*b.y; acc[1][2] += a.y*b.z; acc[1][3] += a.y*b.w;
            acc[2][0] += a.z*b.x; acc[2][1] += a.z*b.y; acc[2][2] += a.z*b.z; acc[2][3] += a.z*b.w;
            acc[3][0] += a.w*b.x; acc[3][1] += a.w*b.y; acc[3][2] += a.w*b.z; acc[3][3] += a.w*b.w;
        }
    }
    int col = n0 + 4*tx;
    #pragma unroll
    for (int i = 0; i < 4; i++) {
        int row = m0 + 4*ty + i;
        float4 v = make_float4(acc[i][0], acc[i][1], acc[i][2], acc[i][3]);
        if (mode == 1) {
            const float* gate = &g_emb[(row >> 10)*(3*CS) + 2*CS];
            v.x = (v.x + bo[col+0]) * gate[col+0];
            v.y = (v.y + bo[col+1]) * gate[col+1];
            v.z = (v.z + bo[col+2]) * gate[col+2];
            v.w = (v.w + bo[col+3]) * gate[col+3];
        }
        *(float4*)&C[(size_t)row*N + col] = v;
    }
}

// ---------------- kernel 5: head split + RMS norm of q,k ----------------
__global__ __launch_bounds__(256) void qkvpost_kernel(const float* __restrict__ rms_q_w,
                                                      const float* __restrict__ rms_k_w) {
    int row = blockIdx.x;           // b*1024+s
    int b = row >> 10, s = row & 1023;
    int w = threadIdx.x >> 5, lane = threadIdx.x & 31;
    for (int hh = w; hh < NH; hh += 8) {
        int src = row*CS + hh*DH + lane;
        int dst = ((b*NH + hh)*S + s)*DH + lane;
        // q
        {
            float v = g_qkvraw[0][src];
            float ss = v*v;
            #pragma unroll
            for (int off = 16; off >= 1; off >>= 1) ss += __shfl_xor_sync(0xffffffffu, ss, off);
            float rs = rsqrtf(ss*(1.f/DH) + EPS);
            g_q[dst] = v * rs * rms_q_w[lane];
        }
        // k
        {
            float v = g_qkvraw[1][src];
            float ss = v*v;
            #pragma unroll
            for (int off = 16; off >= 1; off >>= 1) ss += __shfl_xor_sync(0xffffffffu, ss, off);
            float rs = rsqrtf(ss*(1.f/DH) + EPS);
            g_k[dst] = v * rs * rms_k_w[lane];
        }
        // v
        g_v[dst] = g_qkvraw[2][src];
    }
}

// ---------------- kernel 6: fused z-LN + projection + mask -> per-head bias ----------------
// bias[h,r] = rs*(dot(z_r, A[:,h]) - mu*Ch) + Bh + maskbias      (single pass over z)
__global__ __launch_bounds__(128) void zbias_kernel(const float* __restrict__ z,
                                                    const int* __restrict__ z_mask) {
    __shared__ float sA[CZ*NH];
    __shared__ float sB[NH], sC[NH];
    int tid = threadIdx.x;
    for (int i = tid; i < CZ*NH; i += 128) sA[i] = g_A[i];
    if (tid < NH) { sB[tid] = g_Bh[tid]; sC[tid] = g_Ch[tid]; }
    __syncthreads();

    int r0 = blockIdx.x * 256 + tid;
    int r1 = r0 + 128;
    const float* z0 = z + (size_t)r0 * CZ;
    const float* z1 = z + (size_t)r1 * CZ;
    float acc0[NH] = {}, acc1[NH] = {};
    float s1a = 0.f, s2a = 0.f, s1b = 0.f, s2b = 0.f;

    for (int c4 = 0; c4 < CZ/4; c4++) {
        float4 za = *(const float4*)&z0[c4*4];
        float4 zb = *(const float4*)&z1[c4*4];
        #pragma unroll
        for (int cc = 0; cc < 4; cc++) {
            int c = c4*4 + cc;
            float va = (cc==0)?za.x:(cc==1)?za.y:(cc==2)?za.z:za.w;
            float vb = (cc==0)?zb.x:(cc==1)?zb.y:(cc==2)?zb.z:zb.w;
            s1a += va; s2a += va*va;
            s1b += vb; s2b += vb*vb;
            const float4* ap = (const float4*)&sA[c*NH];
            #pragma unroll
            for (int hq = 0; hq < 6; hq++) {
                float4 aa = ap[hq];
                acc0[hq*4+0] += va*aa.x; acc0[hq*4+1] += va*aa.y;
                acc0[hq*4+2] += va*aa.z; acc0[hq*4+3] += va*aa.w;
                acc1[hq*4+0] += vb*aa.x; acc1[hq*4+1] += vb*aa.y;
                acc1[hq*4+2] += vb*aa.z; acc1[hq*4+3] += vb*aa.w;
            }
        }
    }
    float mu0 = s1a*(1.f/CZ), mu1 = s1b*(1.f/CZ);
    float rs0 = rsqrtf(s2a*(1.f/CZ) - mu0*mu0 + EPS);
    float rs1 = rsqrtf(s2b*(1.f/CZ) - mu1*mu1 + EPS);
    float mb0 = (z_mask[r0] > 0) ? 0.f : NEGINF;
    float mb1 = (z_mask[r1] > 0) ? 0.f : NEGINF;
    #pragma unroll
    for (int h = 0; h < NH; h++) {
        g_bias[h*SSQ + r0] = rs0*(acc0[h] - mu0*sC[h]) + sB[h] + mb0;
        g_bias[h*SSQ + r1] = rs1*(acc1[h] - mu1*sC[h]) + sB[h] + mb1;
    }
}

// ---------------- kernel 7: flash attention with additive bias ----------------
__global__ __launch_bounds__(256) void attn_kernel(const float* __restrict__ beta) {
    __shared__ float Qs[DH][64];
    __shared__ float Ks[DH][64];
    __shared__ float Vs[64][DH];
    __shared__ float Ps[64][68];
    int tid = threadIdx.x;
    int tx = tid & 15, ty = tid >> 4;
    int qt = blockIdx.x, h = blockIdx.y, b = blockIdx.z;

    const float* qb = g_q + ((size_t)(b*NH + h)*S + qt*64)*DH;
    const float* kb = g_k + (size_t)(b*NH + h)*S*DH;
    const float* vb = g_v + (size_t)(b*NH + h)*S*DH;
    const float* biasrow = g_bias + (size_t)h*SSQ + (size_t)(qt*64)*S;
    const float* betarow = beta + (size_t)b*SSQ + (size_t)(qt*64)*S;

    for (int i = tid; i < 512; i += 256) {     // 64 rows * 8 float4
        int r = i >> 3, f = (i & 7) * 4;
        float4 v = *(const float4*)&qb[r*DH + f];
        Qs[f+0][r] = v.x; Qs[f+1][r] = v.y; Qs[f+2][r] = v.z; Qs[f+3][r] = v.w;
    }

    float m_i[4] = {-1e30f, -1e30f, -1e30f, -1e30f};
    float l_i[4] = {0.f, 0.f, 0.f, 0.f};
    float o[4][2] = {};
    const float sc = 0.17677669529663687f;   // 1/sqrt(32)

    for (int kt = 0; kt < 16; kt++) {
        __syncthreads();
        for (int i = tid; i < 512; i += 256) {
            int r = i >> 3, f = (i & 7) * 4;
            float4 v = *(const float4*)&kb[(kt*64 + r)*DH + f];
            Ks[f+0][r] = v.x; Ks[f+1][r] = v.y; Ks[f+2][r] = v.z; Ks[f+3][r] = v.w;
        }
        for (int i = tid; i < 512; i += 256)
            ((float4*)Vs)[i] = ((const float4*)(vb + (size_t)kt*64*DH))[i];
        __syncthreads();

        float s[4][4] = {};
        #pragma unroll
        for (int d = 0; d < DH; d++) {
            float4 a = *(float4*)&Qs[d][4*ty];
            float4 kk = *(float4*)&Ks[d][4*tx];
            s[0][0] += a.x*kk.x; s[0][1] += a.x*kk.y; s[0][2] += a.x*kk.z; s[0][3] += a.x*kk.w;
            s[1][0] += a.y*kk.x; s[1][1] += a.y*kk.y; s[1][2] += a.y*kk.z; s[1][3] += a.y*kk.w;
            s[2][0] += a.z*kk.x; s[2][1] += a.z*kk.y; s[2][2] += a.z*kk.z; s[2][3] += a.z*kk.w;
            s[3][0] += a.w*kk.x; s[3][1] += a.w*kk.y; s[3][2] += a.w*kk.z; s[3][3] += a.w*kk.w;
        }
        #pragma unroll
        for (int i = 0; i < 4; i++) {
            const float* br = &biasrow[(size_t)(4*ty+i)*S + kt*64 + 4*tx];
            const float* be = &betarow[(size_t)(4*ty+i)*S + kt*64 + 4*tx];
            float4 bi = *(const float4*)br;
            float4 bt = *(const float4*)be;
            s[i][0] = s[i][0]*sc + bi.x + bt.x;
            s[i][1] = s[i][1]*sc + bi.y + bt.y;
            s[i][2] = s[i][2]*sc + bi.z + bt.z;
            s[i][3] = s[i][3]*sc + bi.w + bt.w;
        }
        #pragma unroll
        for (int i = 0; i < 4; i++) {
            float tm = fmaxf(fmaxf(s[i][0], s[i][1]), fmaxf(s[i][2], s[i][3]));
            #pragma unroll
            for (int off = 8; off >= 1; off >>= 1)
                tm = fmaxf(tm, __shfl_xor_sync(0xffffffffu, tm, off));
            float mn = fmaxf(m_i[i], tm);
            float al = __expf(m_i[i] - mn);
            m_i[i] = mn;
            float p0 = __expf(s[i][0] - mn);
            float p1 = __expf(s[i][1] - mn);
            float p2 = __expf(s[i][2] - mn);
            float p3 = __expf(s[i][3] - mn);
            float rsum = p0 + p1 + p2 + p3;
            #pragma unroll
            for (int off = 8; off >= 1; off >>= 1)
                rsum += __shfl_xor_sync(0xffffffffu, rsum, off);
            l_i[i] = l_i[i]*al + rsum;
            o[i][0] *= al; o[i][1] *= al;
            *(float4*)&Ps[4*ty + i][4*tx] = make_float4(p0, p1, p2, p3);
        }
        __syncthreads();
        #pragma unroll
        for (int kc = 0; kc < 64; kc += 4) {
            float4 p0 = *(float4*)&Ps[4*ty+0][kc];
            float4 p1 = *(float4*)&Ps[4*ty+1][kc];
            float4 p2 = *(float4*)&Ps[4*ty+2][kc];
            float4 p3 = *(float4*)&Ps[4*ty+3][kc];
            #pragma unroll
            for (int u = 0; u < 4; u++) {
                float2 vv = *(float2*)&Vs[kc+u][2*tx];
                float q0 = (u==0)?p0.x:(u==1)?p0.y:(u==2)?p0.z:p0.w;
                float q1 = (u==0)?p1.x:(u==1)?p1.y:(u==2)?p1.z:p1.w;
                float q2 = (u==0)?p2.x:(u==1)?p2.y:(u==2)?p2.z:p2.w;
                float q3 = (u==0)?p3.x:(u==1)?p3.y:(u==2)?p3.z:p3.w;
                o[0][0] += q0*vv.x; o[0][1] += q0*vv.y;
                o[1][0] += q1*vv.x; o[1][1] += q1*vv.y;
                o[2][0] += q2*vv.x; o[2][1] += q2*vv.y;
                o[3][0] += q3*vv.x; o[3][1] += q3*vv.y;
            }
        }
    }
    #pragma unroll
    for (int i = 0; i < 4; i++) {
        float inv = 1.f / l_i[i];
        int row = b*S + qt*64 + 4*ty + i;
        float2 ov = make_float2(o[i][0]*inv, o[i][1]*inv);
        *(float2*)&g_oat[(size_t)row*CS + h*DH + 2*tx] = ov;
    }
}

// ---------------- host ----------------
extern "C" void kernel_launch(void* const* d_in, const int* in_sizes, int n_in,
                              void* d_out, int out_size) {
    const float* bs      = (const float*)d_in[0];
    const float* z       = (const float*)d_in[1];
    const float* t       = (const float*)d_in[2];
    const float* beta    = (const float*)d_in[3];
    const int*   z_mask  = (const int*)d_in[4];
    const float* w_adaln = (const float*)d_in[5];
    const float* b_adaln = (const float*)d_in[6];
    const float* ln_z_w  = (const float*)d_in[7];
    const float* ln_z_b  = (const float*)d_in[8];
    const float* w_q     = (const float*)d_in[9];
    const float* w_k     = (const float*)d_in[10];
    const float* w_v     = (const float*)d_in[11];
    const float* w_z     = (const float*)d_in[12];
    const float* rms_q_w = (const float*)d_in[13];
    const float* rms_k_w = (const float*)d_in[14];
    const float* w_o     = (const float*)d_in[15];
    const float* b_o     = (const float*)d_in[16];
    float* out = (float*)d_out;

    float *p_bsn, *p_qkv, *p_oat;
    cudaGetSymbolAddress((void**)&p_bsn, g_bsn);
    cudaGetSymbolAddress((void**)&p_qkv, g_qkvraw);
    cudaGetSymbolAddress((void**)&p_oat, g_oat);

    prep_kernel<<<1, 32>>>(ln_z_w, ln_z_b, w_z);
    adaln_kernel<<<dim3(18, 2), 128>>>(t, w_adaln, b_adaln);
    bsnorm_kernel<<<MROWS, 256>>>(bs);

    gemm_kernel<<<dim3(12, 32), 256>>>(p_bsn, w_q, p_qkv + 0*(size_t)MROWS*CS, MROWS, CS, CS, 0, nullptr);
    gemm_kernel<<<dim3(12, 32), 256>>>(p_bsn, w_k, p_qkv + 1*(size_t)MROWS*CS, MROWS, CS, CS, 0, nullptr);
    gemm_kernel<<<dim3(12, 32), 256>>>(p_bsn, w_v, p_qkv + 2*(size_t)MROWS*CS, MROWS, CS, CS, 0, nullptr);
    qkvpost_kernel<<<MROWS, 256>>>(rms_q_w, rms_k_w);

    zbias_kernel<<<4096, 128>>>(z, z_mask);

    attn_kernel<<<dim3(16, NH, NB), 256>>>(beta);

    gemm_kernel<<<dim3(12, 32), 256>>>(p_oat, w_o, out, MROWS, CS, CS, 1, b_o);
}

// round 3
// speedup vs baseline: 1.2318x; 1.2318x over previous
#include <cuda_runtime.h>
#include <cuda_bf16.h>
#include <math.h>
#include <stdint.h>

#define S 1024
#define CS 768
#define CZ 128
#define DH 32
#define NH 24
#define NB 2
#define MROWS (NB*S)     // 2048
#define SSQ (S*S)        // 1048576
#define EPS 1e-5f
#define NEGINF (-1000000000.0f)

// ---------------- scratch (device globals; no allocation allowed) ----------------
__device__ float g_emb[NB*3*CS];                    // shift|scale|gate per batch
__device__ __nv_bfloat16 g_bsn_hi[MROWS*CS];        // modulated LN(bs), bf16 split
__device__ __nv_bfloat16 g_bsn_lo[MROWS*CS];
__device__ __nv_bfloat16 g_wt_hi[4][CS*CS];         // transposed weights [N,K], bf16 split
__device__ __nv_bfloat16 g_wt_lo[4][CS*CS];
__device__ float g_q[NB*NH*S*DH];
__device__ float g_k[NB*NH*S*DH];
__device__ float g_v[NB*NH*S*DH];
__device__ float g_A[CZ*NH];                        // ln_z_w[c]*w_z[c,h]
__device__ float g_Bh[NH];                          // sum_c ln_z_b[c]*w_z[c,h]
__device__ float g_Ch[NH];                          // sum_c A[c,h]
__device__ float g_bias[NH*SSQ];                    // per-head bias incl. mask (100MB)
__device__ __nv_bfloat16 g_oat_hi[MROWS*CS];        // attention output, bf16 split
__device__ __nv_bfloat16 g_oat_lo[MROWS*CS];

// ================= warp-MMA helpers (portable sm_80+ PTX) =================
__device__ __forceinline__ void ldm_x4(uint32_t* r, uint32_t addr) {
    asm volatile("ldmatrix.sync.aligned.m8n8.x4.shared.b16 {%0,%1,%2,%3}, [%4];"
        : "=r"(r[0]), "=r"(r[1]), "=r"(r[2]), "=r"(r[3]) : "r"(addr));
}
__device__ __forceinline__ void mma16816(float* d, const uint32_t* a, const uint32_t* b) {
    asm volatile("mma.sync.aligned.m16n8k16.row.col.f32.bf16.bf16.f32 "
        "{%0,%1,%2,%3}, {%4,%5,%6,%7}, {%8,%9}, {%0,%1,%2,%3};"
        : "+f"(d[0]), "+f"(d[1]), "+f"(d[2]), "+f"(d[3])
        : "r"(a[0]), "r"(a[1]), "r"(a[2]), "r"(a[3]), "r"(b[0]), "r"(b[1]));
}

// ---------------- kernel 1: tiny precompute for z-bias refactor ----------------
__global__ void prep_kernel(const float* __restrict__ ln_z_w,
                            const float* __restrict__ ln_z_b,
                            const float* __restrict__ w_z) {
    int h = threadIdx.x;
    if (h >= NH) return;
    float ch = 0.f, bh = 0.f;
    for (int c = 0; c < CZ; c++) {
        float wz = w_z[c*NH + h];
        float a = ln_z_w[c] * wz;
        g_A[c*NH + h] = a;
        ch += a;
        bh += ln_z_b[c] * wz;
    }
    g_Ch[h] = ch;
    g_Bh[h] = bh;
}

// ---------------- kernel 2: adaLN embedding: silu(t) @ w_adaln + b ----------------
__global__ __launch_bounds__(128) void adaln_kernel(const float* __restrict__ t,
                                                    const float* __restrict__ w_adaln,
                                                    const float* __restrict__ b_adaln) {
    __shared__ float st[CS];
    int b = blockIdx.y;
    int tid = threadIdx.x;
    for (int i = tid; i < CS; i += 128) {
        float v = t[b*CS + i];
        st[i] = v / (1.f + expf(-v));
    }
    __syncthreads();
    int j = blockIdx.x * 128 + tid;
    float acc = b_adaln[j];
    #pragma unroll 4
    for (int i = 0; i < CS; i++)
        acc += st[i] * w_adaln[i*(3*CS) + j];
    g_emb[b*(3*CS) + j] = acc;
}

// ---------------- kernel 3: LN(bs)*(1+scale)+shift -> bf16 hi/lo ----------------
__global__ __launch_bounds__(256) void bsnorm_kernel(const float* __restrict__ bs) {
    __shared__ float red[16];
    int row = blockIdx.x;
    int b = row >> 10;
    int tid = threadIdx.x;
    float x[3];
    float s1 = 0.f, s2 = 0.f;
    #pragma unroll
    for (int j = 0; j < 3; j++) {
        int c = tid + j*256;
        float v = bs[(size_t)row*CS + c];
        x[j] = v;
        s1 += v;
        s2 += v*v;
    }
    #pragma unroll
    for (int off = 16; off >= 1; off >>= 1) {
        s1 += __shfl_xor_sync(0xffffffffu, s1, off);
        s2 += __shfl_xor_sync(0xffffffffu, s2, off);
    }
    int w = tid >> 5;
    if ((tid & 31) == 0) { red[w] = s1; red[8+w] = s2; }
    __syncthreads();
    float t1 = 0.f, t2 = 0.f;
    #pragma unroll
    for (int ww = 0; ww < 8; ww++) { t1 += red[ww]; t2 += red[8+ww]; }
    float mu = t1 * (1.f/CS);
    float var = t2 * (1.f/CS) - mu*mu;
    float rs = rsqrtf(var + EPS);
    #pragma unroll
    for (int j = 0; j < 3; j++) {
        int c = tid + j*256;
        float sc = g_emb[b*(3*CS) + CS + c];
        float sh = g_emb[b*(3*CS) + c];
        float y = (x[j]-mu)*rs*(1.f+sc) + sh;
        __nv_bfloat16 h = __float2bfloat16(y);
        g_bsn_hi[(size_t)row*CS + c] = h;
        g_bsn_lo[(size_t)row*CS + c] = __float2bfloat16(y - __bfloat162float(h));
    }
}

// ---------------- kernel 4: transpose + bf16-split the 4 weights ----------------
__global__ __launch_bounds__(256) void wprep_kernel(const float* __restrict__ w_q,
                                                    const float* __restrict__ w_k,
                                                    const float* __restrict__ w_v,
                                                    const float* __restrict__ w_o) {
    __shared__ float t[32][33];
    int z = blockIdx.z;
    const float* w = (z==0) ? w_q : (z==1) ? w_k : (z==2) ? w_v : w_o;
    __nv_bfloat16* hi = g_wt_hi[z];
    __nv_bfloat16* lo = g_wt_lo[z];
    int n0 = blockIdx.x * 32, k0 = blockIdx.y * 32;
    int x = threadIdx.x, y = threadIdx.y;
    #pragma unroll
    for (int r = 0; r < 4; r++)
        t[y*4+r][x] = w[(size_t)(k0 + y*4 + r)*CS + n0 + x];
    __syncthreads();
    #pragma unroll
    for (int r = 0; r < 4; r++) {
        int n = n0 + y*4 + r, k = k0 + x;
        float v = t[x][y*4+r];
        __nv_bfloat16 h = __float2bfloat16(v);
        hi[(size_t)n*CS + k] = h;
        lo[(size_t)n*CS + k] = __float2bfloat16(v - __bfloat162float(h));
    }
}

// ---------------- kernel 5: HMMA split-bf16 GEMM, 128x64 tile, 8 warps ----------------
// mode 0: QKV combined (N over 3 weight matrices) -> head-split (+RMS for q,k)
// mode 1: out proj -> (acc + b_o) * gate -> o0 [2048,768]
struct __align__(16) GemmSmem {
    union {
        struct {
            __nv_bfloat16 Ah[128][40];
            __nv_bfloat16 Al[128][40];
            __nv_bfloat16 Bh[64][40];
            __nv_bfloat16 Bl[64][40];
        } ld;
        float Cs[128][68];
    };
};
__global__ __launch_bounds__(256) void mma_gemm(const __nv_bfloat16* __restrict__ Ahi,
                                                const __nv_bfloat16* __restrict__ Alo,
                                                const __nv_bfloat16* __restrict__ Bhi,
                                                const __nv_bfloat16* __restrict__ Blo,
                                                float* __restrict__ o0,
                                                float* __restrict__ o1,
                                                float* __restrict__ o2,
                                                const float* __restrict__ aux0,
                                                const float* __restrict__ aux1,
                                                int mode) {
    __shared__ GemmSmem sm;
    int tid = threadIdx.x;
    int w = tid >> 5, lane = tid & 31;
    int m0 = blockIdx.y * 128, n0 = blockIdx.x * 64;
    int mrow = (w & 3) * 32, ncol = (w >> 2) * 32;

    uint32_t sAh = (uint32_t)__cvta_generic_to_shared(&sm.ld.Ah[0][0]);
    uint32_t sAl = (uint32_t)__cvta_generic_to_shared(&sm.ld.Al[0][0]);
    uint32_t sBh = (uint32_t)__cvta_generic_to_shared(&sm.ld.Bh[0][0]);
    uint32_t sBl = (uint32_t)__cvta_generic_to_shared(&sm.ld.Bl[0][0]);

    int arow = lane & 15, acol = (lane >> 4) << 3;
    int brow = (lane & 7) + (((lane >> 4) & 1) << 3), bcol = lane & 8;

    float acc[2][4][4] = {};

    for (int c = 0; c < 24; c++) {
        int k0 = c * 32;
        __syncthreads();
        // load A tile 128x32 hi/lo : 512 uint4 each
        #pragma unroll
        for (int t = 0; t < 2; t++) {
            int i = t*256 + tid;
            int row = i >> 2, seg = (i & 3) * 8;
            size_t src = (size_t)(m0 + row)*CS + k0 + seg;
            *(uint4*)&sm.ld.Ah[row][seg] = *(const uint4*)&Ahi[src];
            *(uint4*)&sm.ld.Al[row][seg] = *(const uint4*)&Alo[src];
        }
        // load B tile 64x32 hi/lo : 256 uint4 each
        {
            int row = tid >> 2, seg = (tid & 3) * 8;
            size_t src = (size_t)(n0 + row)*CS + k0 + seg;
            *(uint4*)&sm.ld.Bh[row][seg] = *(const uint4*)&Bhi[src];
            *(uint4*)&sm.ld.Bl[row][seg] = *(const uint4*)&Blo[src];
        }
        __syncthreads();

        #pragma unroll
        for (int ks = 0; ks < 2; ks++) {
            int k16 = ks * 16;
            uint32_t ah[2][4], al[2][4], bh[2][4], bl[2][4];
            #pragma unroll
            for (int mt = 0; mt < 2; mt++) {
                uint32_t off = (uint32_t)(((mrow + mt*16 + arow)*40 + k16 + acol) * 2);
                ldm_x4(ah[mt], sAh + off);
                ldm_x4(al[mt], sAl + off);
            }
            #pragma unroll
            for (int p = 0; p < 2; p++) {
                uint32_t off = (uint32_t)(((ncol + p*16 + brow)*40 + k16 + bcol) * 2);
                ldm_x4(bh[p], sBh + off);
                ldm_x4(bl[p], sBl + off);
            }
            #pragma unroll
            for (int mt = 0; mt < 2; mt++) {
                #pragma unroll
                for (int nt = 0; nt < 4; nt++) {
                    int p = nt >> 1, o = (nt & 1) * 2;
                    mma16816(acc[mt][nt], ah[mt], &bh[p][o]);
                    mma16816(acc[mt][nt], al[mt], &bh[p][o]);
                    mma16816(acc[mt][nt], ah[mt], &bl[p][o]);
                }
            }
        }
    }

    // stage accumulators to smem
    __syncthreads();
    int grp = lane >> 2, qid = lane & 3;
    #pragma unroll
    for (int mt = 0; mt < 2; mt++) {
        #pragma unroll
        for (int nt = 0; nt < 4; nt++) {
            int rr = mrow + mt*16 + grp;
            int cc = ncol + nt*8 + qid*2;
            sm.Cs[rr][cc]     = acc[mt][nt][0];
            sm.Cs[rr][cc+1]   = acc[mt][nt][1];
            sm.Cs[rr+8][cc]   = acc[mt][nt][2];
            sm.Cs[rr+8][cc+1] = acc[mt][nt][3];
        }
    }
    __syncthreads();

    if (mode == 0) {
        int mat = n0 / CS;
        int h0 = (n0 % CS) >> 5;
        float* base = (mat == 0) ? o0 : (mat == 1) ? o1 : o2;
        const float* rw = (mat == 0) ? aux0 : aux1;
        int h = h0 + (lane >> 4);
        int d = (2*lane) & 31;
        float w0 = (mat == 2) ? 1.f : rw[d];
        float w1 = (mat == 2) ? 1.f : rw[d+1];
        #pragma unroll
        for (int i = 0; i < 16; i++) {
            int rl = w*16 + i;
            int r = m0 + rl, b = r >> 10, s = r & 1023;
            float v0 = sm.Cs[rl][2*lane], v1 = sm.Cs[rl][2*lane+1];
            float ssq = v0*v0 + v1*v1;
            ssq += __shfl_xor_sync(0xffffffffu, ssq, 1);
            ssq += __shfl_xor_sync(0xffffffffu, ssq, 2);
            ssq += __shfl_xor_sync(0xffffffffu, ssq, 4);
            ssq += __shfl_xor_sync(0xffffffffu, ssq, 8);
            float rsn = (mat == 2) ? 1.f : rsqrtf(ssq*(1.f/DH) + EPS);
            float2 ov = make_float2(v0*rsn*w0, v1*rsn*w1);
            *(float2*)&base[(((size_t)b*NH + h)*S + s)*DH + d] = ov;
        }
    } else {
        int col = n0 + 2*lane;
        float b0v = aux0[col], b1v = aux0[col+1];
        #pragma unroll
        for (int i = 0; i < 16; i++) {
            int rl = w*16 + i;
            int r = m0 + rl, b = r >> 10;
            const float* gate = g_emb + b*(3*CS) + 2*CS;
            float v0 = sm.Cs[rl][2*lane], v1 = sm.Cs[rl][2*lane+1];
            float2 ov = make_float2((v0 + b0v) * gate[col], (v1 + b1v) * gate[col+1]);
            *(float2*)&o0[(size_t)r*CS + col] = ov;
        }
    }
}

// ---------------- kernel 6: fused z-LN + projection + mask -> per-head bias ----------------
__global__ __launch_bounds__(128) void zbias_kernel(const float* __restrict__ z,
                                                    const int* __restrict__ z_mask) {
    __shared__ float sA[CZ*NH];
    __shared__ float sB[NH], sC[NH];
    int tid = threadIdx.x;
    for (int i = tid; i < CZ*NH; i += 128) sA[i] = g_A[i];
    if (tid < NH) { sB[tid] = g_Bh[tid]; sC[tid] = g_Ch[tid]; }
    __syncthreads();

    int r0 = blockIdx.x * 256 + tid;
    int r1 = r0 + 128;
    const float* z0 = z + (size_t)r0 * CZ;
    const float* z1 = z + (size_t)r1 * CZ;
    float acc0[NH] = {}, acc1[NH] = {};
    float s1a = 0.f, s2a = 0.f, s1b = 0.f, s2b = 0.f;

    for (int c4 = 0; c4 < CZ/4; c4++) {
        float4 za = *(const float4*)&z0[c4*4];
        float4 zb = *(const float4*)&z1[c4*4];
        #pragma unroll
        for (int cc = 0; cc < 4; cc++) {
            int c = c4*4 + cc;
            float va = (cc==0)?za.x:(cc==1)?za.y:(cc==2)?za.z:za.w;
            float vb = (cc==0)?zb.x:(cc==1)?zb.y:(cc==2)?zb.z:zb.w;
            s1a += va; s2a += va*va;
            s1b += vb; s2b += vb*vb;
            const float4* ap = (const float4*)&sA[c*NH];
            #pragma unroll
            for (int hq = 0; hq < 6; hq++) {
                float4 aa = ap[hq];
                acc0[hq*4+0] += va*aa.x; acc0[hq*4+1] += va*aa.y;
                acc0[hq*4+2] += va*aa.z; acc0[hq*4+3] += va*aa.w;
                acc1[hq*4+0] += vb*aa.x; acc1[hq*4+1] += vb*aa.y;
                acc1[hq*4+2] += vb*aa.z; acc1[hq*4+3] += vb*aa.w;
            }
        }
    }
    float mu0 = s1a*(1.f/CZ), mu1 = s1b*(1.f/CZ);
    float rs0 = rsqrtf(s2a*(1.f/CZ) - mu0*mu0 + EPS);
    float rs1 = rsqrtf(s2b*(1.f/CZ) - mu1*mu1 + EPS);
    float mb0 = (z_mask[r0] > 0) ? 0.f : NEGINF;
    float mb1 = (z_mask[r1] > 0) ? 0.f : NEGINF;
    #pragma unroll
    for (int h = 0; h < NH; h++) {
        g_bias[h*SSQ + r0] = rs0*(acc0[h] - mu0*sC[h]) + sB[h] + mb0;
        g_bias[h*SSQ + r1] = rs1*(acc1[h] - mu1*sC[h]) + sB[h] + mb1;
    }
}

// ---------------- kernel 7: flash attention with additive bias ----------------
__global__ __launch_bounds__(256) void attn_kernel(const float* __restrict__ beta) {
    __shared__ float Qs[DH][64];
    __shared__ float Ks[DH][64];
    __shared__ float Vs[64][DH];
    __shared__ float Ps[64][68];
    int tid = threadIdx.x;
    int tx = tid & 15, ty = tid >> 4;
    int qt = blockIdx.x, h = blockIdx.y, b = blockIdx.z;

    const float* qb = g_q + ((size_t)(b*NH + h)*S + qt*64)*DH;
    const float* kb = g_k + (size_t)(b*NH + h)*S*DH;
    const float* vb = g_v + (size_t)(b*NH + h)*S*DH;
    const float* biasrow = g_bias + (size_t)h*SSQ + (size_t)(qt*64)*S;
    const float* betarow = beta + (size_t)b*SSQ + (size_t)(qt*64)*S;

    for (int i = tid; i < 512; i += 256) {     // 64 rows * 8 float4
        int rr = i >> 3, f = (i & 7) * 4;
        float4 v = *(const float4*)&qb[rr*DH + f];
        Qs[f+0][rr] = v.x; Qs[f+1][rr] = v.y; Qs[f+2][rr] = v.z; Qs[f+3][rr] = v.w;
    }

    float m_i[4] = {-1e30f, -1e30f, -1e30f, -1e30f};
    float l_i[4] = {0.f, 0.f, 0.f, 0.f};
    float o[4][2] = {};
    const float sc = 0.17677669529663687f;   // 1/sqrt(32)

    for (int kt = 0; kt < 16; kt++) {
        __syncthreads();
        for (int i = tid; i < 512; i += 256) {
            int rr = i >> 3, f = (i & 7) * 4;
            float4 v = *(const float4*)&kb[(kt*64 + rr)*DH + f];
            Ks[f+0][rr] = v.x; Ks[f+1][rr] = v.y; Ks[f+2][rr] = v.z; Ks[f+3][rr] = v.w;
        }
        for (int i = tid; i < 512; i += 256)
            ((float4*)Vs)[i] = ((const float4*)(vb + (size_t)kt*64*DH))[i];
        __syncthreads();

        float s[4][4] = {};
        #pragma unroll
        for (int d = 0; d < DH; d++) {
            float4 a = *(float4*)&Qs[d][4*ty];
            float4 kk = *(float4*)&Ks[d][4*tx];
            s[0][0] += a.x*kk.x; s[0][1] += a.x*kk.y; s[0][2] += a.x*kk.z; s[0][3] += a.x*kk.w;
            s[1][0] += a.y*kk.x; s[1][1] += a.y*kk.y; s[1][2] += a.y*kk.z; s[1][3] += a.y*kk.w;
            s[2][0] += a.z*kk.x; s[2][1] += a.z*kk.y; s[2][2] += a.z*kk.z; s[2][3] += a.z*kk.w;
            s[3][0] += a.w*kk.x; s[3][1] += a.w*kk.y; s[3][2] += a.w*kk.z; s[3][3] += a.w*kk.w;
        }
        #pragma unroll
        for (int i = 0; i < 4; i++) {
            const float* br = &biasrow[(size_t)(4*ty+i)*S + kt*64 + 4*tx];
            const float* be = &betarow[(size_t)(4*ty+i)*S + kt*64 + 4*tx];
            float4 bi = *(const float4*)br;
            float4 bt = *(const float4*)be;
            s[i][0] = s[i][0]*sc + bi.x + bt.x;
            s[i][1] = s[i][1]*sc + bi.y + bt.y;
            s[i][2] = s[i][2]*sc + bi.z + bt.z;
            s[i][3] = s[i][3]*sc + bi.w + bt.w;
        }
        #pragma unroll
        for (int i = 0; i < 4; i++) {
            float tm = fmaxf(fmaxf(s[i][0], s[i][1]), fmaxf(s[i][2], s[i][3]));
            #pragma unroll
            for (int off = 8; off >= 1; off >>= 1)
                tm = fmaxf(tm, __shfl_xor_sync(0xffffffffu, tm, off));
            float mn = fmaxf(m_i[i], tm);
            float al = __expf(m_i[i] - mn);
            m_i[i] = mn;
            float p0 = __expf(s[i][0] - mn);
            float p1 = __expf(s[i][1] - mn);
            float p2 = __expf(s[i][2] - mn);
            float p3 = __expf(s[i][3] - mn);
            float rsum = p0 + p1 + p2 + p3;
            #pragma unroll
            for (int off = 8; off >= 1; off >>= 1)
                rsum += __shfl_xor_sync(0xffffffffu, rsum, off);
            l_i[i] = l_i[i]*al + rsum;
            o[i][0] *= al; o[i][1] *= al;
            *(float4*)&Ps[4*ty + i][4*tx] = make_float4(p0, p1, p2, p3);
        }
        __syncthreads();
        #pragma unroll
        for (int kc = 0; kc < 64; kc += 4) {
            float4 p0 = *(float4*)&Ps[4*ty+0][kc];
            float4 p1 = *(float4*)&Ps[4*ty+1][kc];
            float4 p2 = *(float4*)&Ps[4*ty+2][kc];
            float4 p3 = *(float4*)&Ps[4*ty+3][kc];
            #pragma unroll
            for (int u = 0; u < 4; u++) {
                float2 vv = *(float2*)&Vs[kc+u][2*tx];
                float q0 = (u==0)?p0.x:(u==1)?p0.y:(u==2)?p0.z:p0.w;
                float q1 = (u==0)?p1.x:(u==1)?p1.y:(u==2)?p1.z:p1.w;
                float q2 = (u==0)?p2.x:(u==1)?p2.y:(u==2)?p2.z:p2.w;
                float q3 = (u==0)?p3.x:(u==1)?p3.y:(u==2)?p3.z:p3.w;
                o[0][0] += q0*vv.x; o[0][1] += q0*vv.y;
                o[1][0] += q1*vv.x; o[1][1] += q1*vv.y;
                o[2][0] += q2*vv.x; o[2][1] += q2*vv.y;
                o[3][0] += q3*vv.x; o[3][1] += q3*vv.y;
            }
        }
    }
    #pragma unroll
    for (int i = 0; i < 4; i++) {
        float inv = 1.f / l_i[i];
        int row = b*S + qt*64 + 4*ty + i;
        float vx = o[i][0]*inv, vy = o[i][1]*inv;
        size_t idx = (size_t)row*CS + h*DH + 2*tx;
        __nv_bfloat16 hx = __float2bfloat16(vx);
        __nv_bfloat16 hy = __float2bfloat16(vy);
        __nv_bfloat162 hv; hv.x = hx; hv.y = hy;
        __nv_bfloat162 lv;
        lv.x = __float2bfloat16(vx - __bfloat162float(hx));
        lv.y = __float2bfloat16(vy - __bfloat162float(hy));
        *(__nv_bfloat162*)&g_oat_hi[idx] = hv;
        *(__nv_bfloat162*)&g_oat_lo[idx] = lv;
    }
}

// ---------------- host ----------------
extern "C" void kernel_launch(void* const* d_in, const int* in_sizes, int n_in,
                              void* d_out, int out_size) {
    const float* bs      = (const float*)d_in[0];
    const float* z       = (const float*)d_in[1];
    const float* t       = (const float*)d_in[2];
    const float* beta    = (const float*)d_in[3];
    const int*   z_mask  = (const int*)d_in[4];
    const float* w_adaln = (const float*)d_in[5];
    const float* b_adaln = (const float*)d_in[6];
    const float* ln_z_w  = (const float*)d_in[7];
    const float* ln_z_b  = (const float*)d_in[8];
    const float* w_q     = (const float*)d_in[9];
    const float* w_k     = (const float*)d_in[10];
    const float* w_v     = (const float*)d_in[11];
    const float* w_z     = (const float*)d_in[12];
    const float* rms_q_w = (const float*)d_in[13];
    const float* rms_k_w = (const float*)d_in[14];
    const float* w_o     = (const float*)d_in[15];
    const float* b_o     = (const float*)d_in[16];
    float* out = (float*)d_out;

    __nv_bfloat16 *p_bsn_hi, *p_bsn_lo, *p_oat_hi, *p_oat_lo, *p_wt_hi, *p_wt_lo;
    float *p_q, *p_k, *p_v;
    cudaGetSymbolAddress((void**)&p_bsn_hi, g_bsn_hi);
    cudaGetSymbolAddress((void**)&p_bsn_lo, g_bsn_lo);
    cudaGetSymbolAddress((void**)&p_oat_hi, g_oat_hi);
    cudaGetSymbolAddress((void**)&p_oat_lo, g_oat_lo);
    cudaGetSymbolAddress((void**)&p_wt_hi, g_wt_hi);
    cudaGetSymbolAddress((void**)&p_wt_lo, g_wt_lo);
    cudaGetSymbolAddress((void**)&p_q, g_q);
    cudaGetSymbolAddress((void**)&p_k, g_k);
    cudaGetSymbolAddress((void**)&p_v, g_v);

    prep_kernel<<<1, 32>>>(ln_z_w, ln_z_b, w_z);
    adaln_kernel<<<dim3(18, 2), 128>>>(t, w_adaln, b_adaln);
    bsnorm_kernel<<<MROWS, 256>>>(bs);
    wprep_kernel<<<dim3(24, 24, 4), dim3(32, 8)>>>(w_q, w_k, w_v, w_o);

    const size_t WS = (size_t)CS*CS;
    // combined QKV GEMM: N = 2304 (weights 0..2 contiguous in g_wt)
    mma_gemm<<<dim3(36, 16), 256>>>(p_bsn_hi, p_bsn_lo, p_wt_hi, p_wt_lo,
                                    p_q, p_k, p_v, rms_q_w, rms_k_w, 0);

    zbias_kernel<<<4096, 128>>>(z, z_mask);

    attn_kernel<<<dim3(16, NH, NB), 256>>>(beta);

    mma_gemm<<<dim3(12, 16), 256>>>(p_oat_hi, p_oat_lo, p_wt_hi + 3*WS, p_wt_lo + 3*WS,
                                    out, nullptr, nullptr, b_o, nullptr, 1);
}